// round 4
// baseline (speedup 1.0000x reference)
#include <cuda_runtime.h>

#define RP 132
#define EPAD 100096  // 782*128

__device__ float g_xji [(size_t)EPAD * 128];
__device__ float g_xkjd[(size_t)EPAD * 64];
__device__ float g_agg [(size_t)EPAD * 64];
__device__ float g_Wrbfc[768];

typedef unsigned long long u64;

__device__ __forceinline__ float silu_(float x) { return x / (1.0f + __expf(-x)); }
__device__ __forceinline__ u64 pack2(float lo, float hi) {
    u64 d; asm("mov.b64 %0,{%1,%2};" : "=l"(d) : "r"(__float_as_uint(lo)), "r"(__float_as_uint(hi)));
    return d;
}
__device__ __forceinline__ void ffma2(u64& d, u64 a, u64 b) {
    asm("fma.rn.f32x2 %0,%1,%2,%0;" : "+l"(d) : "l"(a), "l"(b));
}
__device__ __forceinline__ float2 unpack2(u64 v) {
    unsigned lo, hi; asm("mov.b64 {%0,%1},%2;" : "=r"(lo), "=r"(hi) : "l"(v));
    return make_float2(__uint_as_float(lo), __uint_as_float(hi));
}

// ---------- R-row x 8-col register-tile GEMM (FFMA2, 4-k blocked) ----------
template <int R, int KK>
__device__ __forceinline__ void gemmRx8(const float* __restrict__ A, const float* __restrict__ B,
                                        const float* __restrict__ bias, int r0, int c0,
                                        u64 (&acc)[R][4]) {
    u64 init[4];
#pragma unroll
    for (int jp = 0; jp < 4; jp++)
        init[jp] = bias ? pack2(bias[c0 + 2 * jp], bias[c0 + 2 * jp + 1]) : 0ull;
#pragma unroll
    for (int i = 0; i < R; i++)
#pragma unroll
        for (int jp = 0; jp < 4; jp++) acc[i][jp] = init[jp];

    for (int k4 = 0; k4 < KK; k4 += 4) {
        float4 av[R];
#pragma unroll
        for (int i = 0; i < R; i++) av[i] = *(const float4*)&A[(r0 + i) * RP + k4];
        ulonglong2 b01[4], b23[4];
#pragma unroll
        for (int kk = 0; kk < 4; kk++) {
            const ulonglong2* bp = (const ulonglong2*)(B + (k4 + kk) * RP + c0);
            b01[kk] = bp[0]; b23[kk] = bp[1];
        }
#pragma unroll
        for (int kk = 0; kk < 4; kk++) {
#pragma unroll
            for (int i = 0; i < R; i++) {
                float a = (kk == 0) ? av[i].x : (kk == 1) ? av[i].y : (kk == 2) ? av[i].z : av[i].w;
                u64 ad = pack2(a, a);
                ffma2(acc[i][0], ad, b01[kk].x);
                ffma2(acc[i][1], ad, b01[kk].y);
                ffma2(acc[i][2], ad, b23[kk].x);
                ffma2(acc[i][3], ad, b23[kk].y);
            }
        }
    }
}

template <int R>
__device__ __forceinline__ void acc_silu_store(const u64 (&acc)[R][4], float* D, int r0, int c0) {
#pragma unroll
    for (int i = 0; i < R; i++) {
        float* d = &D[(r0 + i) * RP + c0];
#pragma unroll
        for (int jp = 0; jp < 4; jp++) {
            float2 p = unpack2(acc[i][jp]);
            d[2 * jp] = silu_(p.x); d[2 * jp + 1] = silu_(p.y);
        }
    }
}
template <int R>
__device__ __forceinline__ void acc_silu_add(const u64 (&acc)[R][4], float* D, int r0, int c0) {
#pragma unroll
    for (int i = 0; i < R; i++) {
        float* d = &D[(r0 + i) * RP + c0];
#pragma unroll
        for (int jp = 0; jp < 4; jp++) {
            float2 p = unpack2(acc[i][jp]);
            d[2 * jp] += silu_(p.x); d[2 * jp + 1] += silu_(p.y);
        }
    }
}

// ---------------- K0: W_rbfc = W_rbf1 @ W_rbf2 ----------------
__global__ void k_wcomb(const float* __restrict__ W1, const float* __restrict__ W2) {
    int i = blockIdx.x * blockDim.x + threadIdx.x;
    if (i < 768) {
        int r = i >> 7, c = i & 127;
        float s = 0.f;
#pragma unroll
        for (int b = 0; b < 8; b++) s += W1[r * 8 + b] * W2[b * 128 + c];
        g_Wrbfc[i] = s;
    }
}

// ---------------- K1: edge preprocess (512 threads) ----------------
__global__ void __launch_bounds__(512, 1)
k_edge_pre(const float* __restrict__ x1, const float* __restrict__ rbf0,
           const float* __restrict__ Wji, const float* __restrict__ bji,
           const float* __restrict__ Wkj, const float* __restrict__ bkj,
           const float* __restrict__ Wdown, int E) {
    extern __shared__ float sm[];
    float* As = sm;
    float* Bs = As + 128 * RP;
    float* Wc = Bs + 128 * RP;
    float* Rb = Wc + 768;
    const int tid = threadIdx.x;
    const int tile0 = blockIdx.x * 128;
    const int r0 = (tid >> 4) * 4, c0 = (tid & 15) * 8;

    {
        float4 z = make_float4(0.f, 0.f, 0.f, 0.f);
        for (int i = tid; i < 128 * 16; i += 512) {
            int r = i >> 4, c4 = (i & 15) * 4;
            *(float4*)&g_agg[(size_t)(tile0 + r) * 64 + c4] = z;
        }
    }
    for (int i = tid; i < 128 * 32; i += 512) {
        int r = i >> 5, c4 = (i & 31) * 4;
        int row = tile0 + r;
        float4 v = make_float4(0.f, 0.f, 0.f, 0.f);
        if (row < E) v = *(const float4*)&x1[(size_t)row * 128 + c4];
        *(float4*)&As[r * RP + c4] = v;
    }
    for (int i = tid; i < 768; i += 512) Wc[i] = g_Wrbfc[i];
    for (int i = tid; i < 128 * 6; i += 512) {
        int r = i / 6, q = i - 6 * r;
        int row = tile0 + r;
        Rb[r * 8 + q] = (row < E) ? rbf0[(size_t)row * 6 + q] : 0.f;
    }
    for (int i = tid; i < 128 * 32; i += 512) {
        int k = i >> 5, c4 = (i & 31) * 4;
        *(float4*)&Bs[k * RP + c4] = *(const float4*)&Wji[k * 128 + c4];
    }
    __syncthreads();

    u64 acc[4][4];
    gemmRx8<4, 128>(As, Bs, bji, r0, c0, acc);
#pragma unroll
    for (int i = 0; i < 4; i++) {
        int row = tile0 + r0 + i;
        float2 p0 = unpack2(acc[i][0]), p1 = unpack2(acc[i][1]);
        float2 p2 = unpack2(acc[i][2]), p3 = unpack2(acc[i][3]);
        *(float4*)&g_xji[(size_t)row * 128 + c0] =
            make_float4(silu_(p0.x), silu_(p0.y), silu_(p1.x), silu_(p1.y));
        *(float4*)&g_xji[(size_t)row * 128 + c0 + 4] =
            make_float4(silu_(p2.x), silu_(p2.y), silu_(p3.x), silu_(p3.y));
    }
    __syncthreads();
    for (int i = tid; i < 128 * 32; i += 512) {
        int k = i >> 5, c4 = (i & 31) * 4;
        *(float4*)&Bs[k * RP + c4] = *(const float4*)&Wkj[k * 128 + c4];
    }
    __syncthreads();
    gemmRx8<4, 128>(As, Bs, bkj, r0, c0, acc);
    __syncthreads();  // all As reads done before overwrite
#pragma unroll
    for (int i = 0; i < 4; i++) {
        float rv[6];
#pragma unroll
        for (int q = 0; q < 6; q++) rv[q] = Rb[(r0 + i) * 8 + q];
        float* d = &As[(r0 + i) * RP + c0];
#pragma unroll
        for (int jp = 0; jp < 4; jp++) {
            float2 p = unpack2(acc[i][jp]);
            int cA = c0 + 2 * jp;
            float f0 = 0.f, f1 = 0.f;
#pragma unroll
            for (int q = 0; q < 6; q++) {
                f0 += rv[q] * Wc[q * 128 + cA];
                f1 += rv[q] * Wc[q * 128 + cA + 1];
            }
            d[2 * jp] = silu_(p.x) * f0;
            d[2 * jp + 1] = silu_(p.y) * f1;
        }
    }
    __syncthreads();
    for (int i = tid; i < 128 * 16; i += 512) {
        int k = i >> 4, c4 = (i & 15) * 4;
        *(float4*)&Bs[k * RP + c4] = *(const float4*)&Wdown[k * 64 + c4];
    }
    __syncthreads();
    u64 a2[2][4];
    const int rr0 = (tid >> 3) * 2, cc0 = (tid & 7) * 8;
    gemmRx8<2, 128>(As, Bs, (const float*)0, rr0, cc0, a2);
#pragma unroll
    for (int i = 0; i < 2; i++) {
        int row = tile0 + rr0 + i;
        float2 p0 = unpack2(a2[i][0]), p1 = unpack2(a2[i][1]);
        float2 p2 = unpack2(a2[i][2]), p3 = unpack2(a2[i][3]);
        *(float4*)&g_xkjd[(size_t)row * 64 + cc0] =
            make_float4(silu_(p0.x), silu_(p0.y), silu_(p1.x), silu_(p1.y));
        *(float4*)&g_xkjd[(size_t)row * 64 + cc0 + 4] =
            make_float4(silu_(p2.x), silu_(p2.y), silu_(p3.x), silu_(p3.y));
    }
}

// ---------------- K2: persistent triplet messages + scatter ----------------
__global__ void __launch_bounds__(256)
k_triplet(const float* __restrict__ sbf, const float* __restrict__ tb,
          const int* __restrict__ idx_kj, const int* __restrict__ idx_ji,
          const float* __restrict__ Ws1, const float* __restrict__ Ws2,
          const float* __restrict__ Wt1, const float* __restrict__ Wt2,
          int T, int nchunks) {
    extern __shared__ float sm[];
    float* TB  = sm;              // 32*296
    float* SB  = TB + 32 * 296;   // 32*44
    float* W1T = SB + 32 * 44;    // 8*300
    float* S1T = W1T + 8 * 300;   // 8*44
    float* WT2 = S1T + 8 * 44;    // 512
    float* WS2 = WT2 + 512;       // 512
    float* TMT = WS2 + 512;       // 256
    float* TMS = TMT + 256;       // 256
    int* IK = (int*)(TMS + 256);
    int* IJ = IK + 32;
    const int tid = threadIdx.x;

    // weights once per block
    for (int i = tid; i < 8 * 300; i += 256) { int c = i / 300, r = i - 300 * c; W1T[i] = (r < 294) ? Wt1[r * 8 + c] : 0.f; }
    for (int i = tid; i < 8 * 44; i += 256)  { int c = i / 44,  r = i - 44 * c;  S1T[i] = (r < 42)  ? Ws1[r * 8 + c] : 0.f; }
    for (int i = tid; i < 512; i += 256) { WT2[i] = Wt2[i]; WS2[i] = Ws2[i]; }
    if (tid < 32) {
        TB[tid * 296 + 294] = 0.f; TB[tid * 296 + 295] = 0.f;
        SB[tid * 44 + 42] = 0.f;   SB[tid * 44 + 43] = 0.f;
    }
    __syncthreads();

    const int tr = tid >> 3, c = tid & 7;
    const int c8 = (tid & 7) * 8;

    for (int ch = blockIdx.x; ch < nchunks; ch += gridDim.x) {
        const int t0 = ch * 32;
        int nrows = T - t0; if (nrows > 32) nrows = 32;

        if (tid < 32) {
            int t = t0 + tid;
            IK[tid] = (t < T) ? idx_kj[t] : 0;
            IJ[tid] = (t < T) ? idx_ji[t] : 0;
        }
        {
            const float* src = tb + (size_t)t0 * 294;
            int lim = nrows * 294;
            for (int i4 = tid; i4 < 2352; i4 += 256) {
                int e = i4 * 4; float vv[4] = {0.f, 0.f, 0.f, 0.f};
                if (e + 4 <= lim) { float4 v = *(const float4*)(src + e); vv[0] = v.x; vv[1] = v.y; vv[2] = v.z; vv[3] = v.w; }
                else { for (int j = 0; j < 4; j++) if (e + j < lim) vv[j] = src[e + j]; }
#pragma unroll
                for (int j = 0; j < 4; j++) { int ee = e + j; int r = ee / 294, cc = ee - 294 * r; TB[r * 296 + cc] = vv[j]; }
            }
            const float* ss = sbf + (size_t)t0 * 42;
            int lim2 = nrows * 42;
            for (int i4 = tid; i4 < 336; i4 += 256) {
                int e = i4 * 4; float vv[4] = {0.f, 0.f, 0.f, 0.f};
                if (e + 4 <= lim2) { float4 v = *(const float4*)(ss + e); vv[0] = v.x; vv[1] = v.y; vv[2] = v.z; vv[3] = v.w; }
                else { for (int j = 0; j < 4; j++) if (e + j < lim2) vv[j] = ss[e + j]; }
#pragma unroll
                for (int j = 0; j < 4; j++) { int ee = e + j; int r = ee / 42, cc = ee - 42 * r; SB[r * 44 + cc] = vv[j]; }
            }
        }
        __syncthreads();
        {
            const ulonglong2* a = (const ulonglong2*)(TB + tr * 296);
            const ulonglong2* w = (const ulonglong2*)(W1T + c * 300);
            u64 ac0 = 0, ac1 = 0;
#pragma unroll 4
            for (int r = 0; r < 74; r++) { ulonglong2 x = a[r], y = w[r]; ffma2(ac0, x.x, y.x); ffma2(ac1, x.y, y.y); }
            float2 p = unpack2(ac0), q = unpack2(ac1);
            TMT[tr * 8 + c] = p.x + p.y + q.x + q.y;
            const ulonglong2* s2 = (const ulonglong2*)(SB + tr * 44);
            const ulonglong2* w2 = (const ulonglong2*)(S1T + c * 44);
            u64 b0 = 0, b1 = 0;
#pragma unroll
            for (int r = 0; r < 11; r++) { ulonglong2 x = s2[r], y = w2[r]; ffma2(b0, x.x, y.x); ffma2(b1, x.y, y.y); }
            float2 s = unpack2(b0), t2 = unpack2(b1);
            TMS[tr * 8 + c] = s.x + s.y + t2.x + t2.y;
        }
        __syncthreads();
        if (t0 + tr < T) {
            u64 tp[4] = {0, 0, 0, 0}, sp[4] = {0, 0, 0, 0};
#pragma unroll
            for (int r = 0; r < 8; r++) {
                float at = TMT[tr * 8 + r], bs = TMS[tr * 8 + r];
                u64 a = pack2(at, at), b = pack2(bs, bs);
                const ulonglong2* w2 = (const ulonglong2*)(WT2 + r * 64 + c8);
                const ulonglong2* v2 = (const ulonglong2*)(WS2 + r * 64 + c8);
                ulonglong2 wA = w2[0], wB = w2[1], vA = v2[0], vB = v2[1];
                ffma2(tp[0], a, wA.x); ffma2(tp[1], a, wA.y); ffma2(tp[2], a, wB.x); ffma2(tp[3], a, wB.y);
                ffma2(sp[0], b, vA.x); ffma2(sp[1], b, vA.y); ffma2(sp[2], b, vB.x); ffma2(sp[3], b, vB.y);
            }
            size_t gk = (size_t)IK[tr] * 64 + c8;
            float4 g0 = *(const float4*)&g_xkjd[gk];
            float4 g1 = *(const float4*)&g_xkjd[gk + 4];
            float gg[8] = {g0.x, g0.y, g0.z, g0.w, g1.x, g1.y, g1.z, g1.w};
            float* dst = &g_agg[(size_t)IJ[tr] * 64 + c8];
#pragma unroll
            for (int jp = 0; jp < 4; jp++) {
                float2 tv = unpack2(tp[jp]), sv = unpack2(sp[jp]);
                atomicAdd(dst + 2 * jp,     tv.x * sv.x * gg[2 * jp]);
                atomicAdd(dst + 2 * jp + 1, tv.y * sv.y * gg[2 * jp + 1]);
            }
        }
        __syncthreads();
    }
}

// ---------------- K3: edge epilogue chain (512 threads) ----------------
#define LOADB(W) do { \
    for (int i = tid; i < 128 * 32; i += 512) { \
        int k = i >> 5, c4 = (i & 31) * 4; \
        *(float4*)&Bs[k * RP + c4] = *(const float4*)&(W)[k * 128 + c4]; \
    } } while (0)

#define RESID(SRC, TMP, W1, B1, W2, B2) do { \
    LOADB(W1); __syncthreads(); \
    gemmRx8<4, 128>(SRC, Bs, (B1), r0, c0, acc); \
    acc_silu_store<4>(acc, TMP, r0, c0); __syncthreads(); \
    LOADB(W2); __syncthreads(); \
    gemmRx8<4, 128>(TMP, Bs, (B2), r0, c0, acc); \
    acc_silu_add<4>(acc, SRC, r0, c0); __syncthreads(); \
} while (0)

__global__ void __launch_bounds__(512, 1)
k_edge_post(const float* __restrict__ x1, const float* __restrict__ rbf0,
            const float* __restrict__ Wup,
            const float* __restrict__ rbW1, const float* __restrict__ rbb1,
            const float* __restrict__ rbW2, const float* __restrict__ rbb2,
            const float* __restrict__ Wlin, const float* __restrict__ blin,
            const float* __restrict__ raW1, const float* __restrict__ rab1,
            const float* __restrict__ raW2, const float* __restrict__ rab2,
            const float* __restrict__ Wr_g, float* __restrict__ out, int E) {
    extern __shared__ float sm[];
    float* P = sm;
    float* Q = P + 128 * RP;
    float* Bs = Q + 128 * RP;
    float* Wr = Bs + 128 * RP;
    float* Rb = Wr + 768;
    const int tid = threadIdx.x;
    const int tile0 = blockIdx.x * 128;
    const int r0 = (tid >> 4) * 4, c0 = (tid & 15) * 8;

    for (int i = tid; i < 128 * 16; i += 512) {
        int r = i >> 4, c4 = (i & 15) * 4;
        *(float4*)&P[r * RP + c4] = *(const float4*)&g_agg[(size_t)(tile0 + r) * 64 + c4];
    }
    for (int i = tid; i < 768; i += 512) Wr[i] = Wr_g[i];
    for (int i = tid; i < 128 * 6; i += 512) {
        int r = i / 6, q = i - 6 * r;
        int row = tile0 + r;
        Rb[r * 8 + q] = (row < E) ? rbf0[(size_t)row * 6 + q] : 0.f;
    }
    for (int i = tid; i < 64 * 32; i += 512) {
        int k = i >> 5, c4 = (i & 31) * 4;
        *(float4*)&Bs[k * RP + c4] = *(const float4*)&Wup[k * 128 + c4];
    }
    __syncthreads();
    u64 acc[4][4];
    gemmRx8<4, 64>(P, Bs, (const float*)0, r0, c0, acc);
#pragma unroll
    for (int i = 0; i < 4; i++) {
        int row = tile0 + r0 + i;
        float4 j0 = *(const float4*)&g_xji[(size_t)row * 128 + c0];
        float4 j1 = *(const float4*)&g_xji[(size_t)row * 128 + c0 + 4];
        float2 p0 = unpack2(acc[i][0]), p1 = unpack2(acc[i][1]);
        float2 p2 = unpack2(acc[i][2]), p3 = unpack2(acc[i][3]);
        float* d = &Q[(r0 + i) * RP + c0];
        d[0] = j0.x + silu_(p0.x); d[1] = j0.y + silu_(p0.y);
        d[2] = j0.z + silu_(p1.x); d[3] = j0.w + silu_(p1.y);
        d[4] = j1.x + silu_(p2.x); d[5] = j1.y + silu_(p2.y);
        d[6] = j1.z + silu_(p3.x); d[7] = j1.w + silu_(p3.y);
    }
    __syncthreads();

    RESID(Q, P, rbW1, rbb1, rbW2, rbb2);

    LOADB(Wlin); __syncthreads();
    gemmRx8<4, 128>(Q, Bs, blin, r0, c0, acc);
#pragma unroll
    for (int i = 0; i < 4; i++) {
        int row = tile0 + r0 + i;
        float4 xv0 = make_float4(0.f, 0.f, 0.f, 0.f), xv1 = xv0;
        if (row < E) {
            xv0 = *(const float4*)&x1[(size_t)row * 128 + c0];
            xv1 = *(const float4*)&x1[(size_t)row * 128 + c0 + 4];
        }
        float2 p0 = unpack2(acc[i][0]), p1 = unpack2(acc[i][1]);
        float2 p2 = unpack2(acc[i][2]), p3 = unpack2(acc[i][3]);
        float* d = &P[(r0 + i) * RP + c0];
        d[0] = silu_(p0.x) + xv0.x; d[1] = silu_(p0.y) + xv0.y;
        d[2] = silu_(p1.x) + xv0.z; d[3] = silu_(p1.y) + xv0.w;
        d[4] = silu_(p2.x) + xv1.x; d[5] = silu_(p2.y) + xv1.y;
        d[6] = silu_(p3.x) + xv1.z; d[7] = silu_(p3.y) + xv1.w;
    }
    __syncthreads();

    RESID(P, Q, raW1, rab1, raW2, rab2);
    RESID(P, Q, raW1 + 16384, rab1 + 128, raW2 + 16384, rab2 + 128);

#pragma unroll
    for (int i = 0; i < 4; i++) {
        int row = tile0 + r0 + i;
        if (row >= E) continue;
        const float* p = &P[(r0 + i) * RP + c0];
        float rv[6];
#pragma unroll
        for (int q = 0; q < 6; q++) rv[q] = Rb[(r0 + i) * 8 + q];
        float e1v[8], e2v[8];
#pragma unroll
        for (int j = 0; j < 8; j++) {
            float f = 0.f; int cc = c0 + j;
#pragma unroll
            for (int q = 0; q < 6; q++) f += rv[q] * Wr[q * 128 + cc];
            e1v[j] = p[j]; e2v[j] = f * p[j];
        }
        *(float4*)&out[(size_t)row * 128 + c0]     = make_float4(e1v[0], e1v[1], e1v[2], e1v[3]);
        *(float4*)&out[(size_t)row * 128 + c0 + 4] = make_float4(e1v[4], e1v[5], e1v[6], e1v[7]);
        *(float4*)&out[((size_t)E + row) * 128 + c0]     = make_float4(e2v[0], e2v[1], e2v[2], e2v[3]);
        *(float4*)&out[((size_t)E + row) * 128 + c0 + 4] = make_float4(e2v[4], e2v[5], e2v[6], e2v[7]);
    }
}

extern "C" void kernel_launch(void* const* d_in, const int* in_sizes, int n_in,
                              void* d_out, int out_size) {
    const float* x1    = (const float*)d_in[0];
    const float* rbf0  = (const float*)d_in[1];
    const float* sbf   = (const float*)d_in[2];
    const float* tb    = (const float*)d_in[3];
    const int* idx_kj  = (const int*)d_in[4];
    const int* idx_ji  = (const int*)d_in[5];
    const float* W_rbf1 = (const float*)d_in[6];
    const float* W_rbf2 = (const float*)d_in[7];
    const float* W_sbf1 = (const float*)d_in[8];
    const float* W_sbf2 = (const float*)d_in[9];
    const float* W_t1   = (const float*)d_in[10];
    const float* W_t2   = (const float*)d_in[11];
    const float* W_rbf  = (const float*)d_in[12];
    const float* W_kj   = (const float*)d_in[13];
    const float* b_kj   = (const float*)d_in[14];
    const float* W_ji   = (const float*)d_in[15];
    const float* b_ji   = (const float*)d_in[16];
    const float* W_down = (const float*)d_in[17];
    const float* W_up   = (const float*)d_in[18];
    const float* rbW1   = (const float*)d_in[19];
    const float* rbb1   = (const float*)d_in[20];
    const float* rbW2   = (const float*)d_in[21];
    const float* rbb2   = (const float*)d_in[22];
    const float* W_lin  = (const float*)d_in[23];
    const float* b_lin  = (const float*)d_in[24];
    const float* raW1   = (const float*)d_in[25];
    const float* rab1   = (const float*)d_in[26];
    const float* raW2   = (const float*)d_in[27];
    const float* rab2   = (const float*)d_in[28];
    float* out = (float*)d_out;

    const int E = in_sizes[0] / 128;
    const int T = in_sizes[4];
    const int SM_PRE  = (2 * 128 * RP + 768 + 1024) * 4;   // 142336
    const int SM_POST = (3 * 128 * RP + 768 + 1024) * 4;   // 209920
    const int SM_TRI  = 60928;
    const int etiles = (E + 127) / 128;
    const int nchunks = (T + 31) / 32;
    const int tri_blocks = 444;   // 3 CTAs/SM x 148

    cudaFuncSetAttribute(k_edge_pre,  cudaFuncAttributeMaxDynamicSharedMemorySize, SM_PRE);
    cudaFuncSetAttribute(k_triplet,   cudaFuncAttributeMaxDynamicSharedMemorySize, SM_TRI);
    cudaFuncSetAttribute(k_edge_post, cudaFuncAttributeMaxDynamicSharedMemorySize, SM_POST);

    k_wcomb<<<3, 256>>>(W_rbf1, W_rbf2);
    k_edge_pre<<<etiles, 512, SM_PRE>>>(x1, rbf0, W_ji, b_ji, W_kj, b_kj, W_down, E);
    k_triplet<<<tri_blocks, 256, SM_TRI>>>(sbf, tb, idx_kj, idx_ji, W_sbf1, W_sbf2, W_t1, W_t2, T, nchunks);
    k_edge_post<<<etiles, 512, SM_POST>>>(x1, rbf0, W_up, rbW1, rbb1, rbW2, rbb2,
                                          W_lin, b_lin, raW1, rab1, raW2, rab2, W_rbf, out, E);
}

// round 8
// speedup vs baseline: 1.0979x; 1.0979x over previous
#include <cuda_runtime.h>
#include <cuda_bf16.h>
#include <mma.h>
#include <cstdint>

using namespace nvcuda;

#define RP 132
#define LDB 136
#define EPAD 100096  // 782*128

__device__ float g_xji [(size_t)EPAD * 128];
__device__ float g_xkjd[(size_t)EPAD * 64];
__device__ float g_agg [(size_t)EPAD * 64];
__device__ float g_Wrbfc[768];
// bf16 hi/lo weight images, padded row-major [K][136]:
// 7 K=128 matrices: rbW1, rbW2, Wlin, raW1a, raW2a, raW1b, raW2b
__device__ __align__(16) __nv_bfloat16 g_Wph[7 * 128 * LDB];
__device__ __align__(16) __nv_bfloat16 g_Wpl[7 * 128 * LDB];
__device__ __align__(16) __nv_bfloat16 g_Wuph[64 * LDB];
__device__ __align__(16) __nv_bfloat16 g_Wupl[64 * LDB];

extern __shared__ char smraw[];

typedef unsigned long long u64;

__device__ __forceinline__ float silu_(float x) { return x / (1.0f + __expf(-x)); }
__device__ __forceinline__ u64 pack2(float lo, float hi) {
    u64 d; asm("mov.b64 %0,{%1,%2};" : "=l"(d) : "r"(__float_as_uint(lo)), "r"(__float_as_uint(hi)));
    return d;
}
__device__ __forceinline__ void ffma2(u64& d, u64 a, u64 b) {
    asm("fma.rn.f32x2 %0,%1,%2,%0;" : "+l"(d) : "l"(a), "l"(b));
}
__device__ __forceinline__ float2 unpack2(u64 v) {
    unsigned lo, hi; asm("mov.b64 {%0,%1},%2;" : "=r"(lo), "=r"(hi) : "l"(v));
    return make_float2(__uint_as_float(lo), __uint_as_float(hi));
}
__device__ __forceinline__ uint32_t smem_to_u32(const void* p) {
    uint32_t a;
    asm("{ .reg .u64 t; cvta.to.shared.u64 t, %1; cvt.u32.u64 %0, t; }" : "=r"(a) : "l"(p));
    return a;
}
__device__ __forceinline__ void stsPairE(__nv_bfloat16* H, __nv_bfloat16* L, int eoff, float v0, float v1) {
    __nv_bfloat162 hp, lp;
    hp.x = __float2bfloat16(v0); hp.y = __float2bfloat16(v1);
    lp.x = __float2bfloat16(v0 - __bfloat162float(hp.x));
    lp.y = __float2bfloat16(v1 - __bfloat162float(hp.y));
    *(__nv_bfloat162*)(H + eoff) = hp;
    *(__nv_bfloat162*)(L + eoff) = lp;
}
__device__ __forceinline__ float2 ldPairE(const __nv_bfloat16* H, const __nv_bfloat16* L, int eoff) {
    __nv_bfloat162 h = *(const __nv_bfloat162*)(H + eoff);
    __nv_bfloat162 l = *(const __nv_bfloat162*)(L + eoff);
    return make_float2(__bfloat162float(h.x) + __bfloat162float(l.x),
                       __bfloat162float(h.y) + __bfloat162float(l.y));
}
// cp.async 16B prefetch of hi/lo weight images into the W smem buffers
__device__ __forceinline__ void cpW(uint32_t whU, uint32_t wlU,
                                    const char* sh, const char* sl, int bytes, int tid) {
    for (int i = tid * 16; i < bytes; i += 256 * 16) {
        asm volatile("cp.async.cg.shared.global [%0],[%1],16;" :: "r"(whU + i), "l"(sh + i) : "memory");
        asm volatile("cp.async.cg.shared.global [%0],[%1],16;" :: "r"(wlU + i), "l"(sl + i) : "memory");
    }
}
#define CP_COMMIT() asm volatile("cp.async.commit_group;" ::: "memory")
#define CP_WAIT0()  asm volatile("cp.async.wait_group 0;" ::: "memory")

// ---------------- K0a: W_rbfc = W_rbf1 @ W_rbf2 ----------------
__global__ void k_wcomb(const float* __restrict__ W1, const float* __restrict__ W2) {
    int i = blockIdx.x * blockDim.x + threadIdx.x;
    if (i < 768) {
        int r = i >> 7, c = i & 127;
        float s = 0.f;
#pragma unroll
        for (int b = 0; b < 8; b++) s += W1[r * 8 + b] * W2[b * 128 + c];
        g_Wrbfc[i] = s;
    }
}

// ---------------- K0b: weights -> padded bf16 hi/lo images ----------------
__global__ void k_wprep(const float* __restrict__ rbW1, const float* __restrict__ rbW2,
                        const float* __restrict__ Wlin, const float* __restrict__ raW1,
                        const float* __restrict__ raW2, const float* __restrict__ Wup) {
    int i = blockIdx.x * blockDim.x + threadIdx.x;
    const int PER = 128 * LDB;
    if (i < 7 * PER) {
        int s = i / PER, e = i - s * PER;
        int k = e / LDB, n = e - k * LDB;
        const float* W = (s == 0) ? rbW1 : (s == 1) ? rbW2 : (s == 2) ? Wlin :
                         (s == 3) ? raW1 : (s == 4) ? raW2 : (s == 5) ? raW1 + 16384 : raW2 + 16384;
        float v = (n < 128) ? W[k * 128 + n] : 0.f;
        __nv_bfloat16 h = __float2bfloat16(v);
        g_Wph[i] = h;
        g_Wpl[i] = __float2bfloat16(v - __bfloat162float(h));
    } else if (i < 7 * PER + 64 * LDB) {
        int e = i - 7 * PER;
        int k = e / LDB, n = e - k * LDB;
        float v = (n < 128) ? Wup[k * 128 + n] : 0.f;
        __nv_bfloat16 h = __float2bfloat16(v);
        g_Wuph[e] = h;
        g_Wupl[e] = __float2bfloat16(v - __bfloat162float(h));
    }
}

// ---------- R-row x 8-col register-tile GEMM (FFMA2) for k_edge_pre ----------
template <int R, int KK>
__device__ __forceinline__ void gemmRx8(const float* __restrict__ A, const float* __restrict__ B,
                                        const float* __restrict__ bias, int r0, int c0,
                                        u64 (&acc)[R][4]) {
    u64 init[4];
#pragma unroll
    for (int jp = 0; jp < 4; jp++)
        init[jp] = bias ? pack2(bias[c0 + 2 * jp], bias[c0 + 2 * jp + 1]) : 0ull;
#pragma unroll
    for (int i = 0; i < R; i++)
#pragma unroll
        for (int jp = 0; jp < 4; jp++) acc[i][jp] = init[jp];
    for (int k4 = 0; k4 < KK; k4 += 4) {
        float4 av[R];
#pragma unroll
        for (int i = 0; i < R; i++) av[i] = *(const float4*)&A[(r0 + i) * RP + k4];
        ulonglong2 b01[4], b23[4];
#pragma unroll
        for (int kk = 0; kk < 4; kk++) {
            const ulonglong2* bp = (const ulonglong2*)(B + (k4 + kk) * RP + c0);
            b01[kk] = bp[0]; b23[kk] = bp[1];
        }
#pragma unroll
        for (int kk = 0; kk < 4; kk++) {
#pragma unroll
            for (int i = 0; i < R; i++) {
                float a = (kk == 0) ? av[i].x : (kk == 1) ? av[i].y : (kk == 2) ? av[i].z : av[i].w;
                u64 ad = pack2(a, a);
                ffma2(acc[i][0], ad, b01[kk].x);
                ffma2(acc[i][1], ad, b01[kk].y);
                ffma2(acc[i][2], ad, b23[kk].x);
                ffma2(acc[i][3], ad, b23[kk].y);
            }
        }
    }
}

// ---------------- K1: edge preprocess (512 threads, FFMA2) ----------------
__global__ void __launch_bounds__(512, 1)
k_edge_pre(const float* __restrict__ x1, const float* __restrict__ rbf0,
           const float* __restrict__ Wji, const float* __restrict__ bji,
           const float* __restrict__ Wkj, const float* __restrict__ bkj,
           const float* __restrict__ Wdown, int E) {
    float* sm = (float*)smraw;
    float* As = sm;
    float* Bs = As + 128 * RP;
    float* Wc = Bs + 128 * RP;
    float* Rb = Wc + 768;
    const int tid = threadIdx.x;
    const int tile0 = blockIdx.x * 128;
    const int r0 = (tid >> 4) * 4, c0 = (tid & 15) * 8;

    {
        float4 z = make_float4(0.f, 0.f, 0.f, 0.f);
        for (int i = tid; i < 128 * 16; i += 512) {
            int r = i >> 4, c4 = (i & 15) * 4;
            *(float4*)&g_agg[(size_t)(tile0 + r) * 64 + c4] = z;
        }
    }
    for (int i = tid; i < 128 * 32; i += 512) {
        int r = i >> 5, c4 = (i & 31) * 4;
        int row = tile0 + r;
        float4 v = make_float4(0.f, 0.f, 0.f, 0.f);
        if (row < E) v = *(const float4*)&x1[(size_t)row * 128 + c4];
        *(float4*)&As[r * RP + c4] = v;
    }
    for (int i = tid; i < 768; i += 512) Wc[i] = g_Wrbfc[i];
    for (int i = tid; i < 128 * 6; i += 512) {
        int r = i / 6, q = i - 6 * r;
        int row = tile0 + r;
        Rb[r * 8 + q] = (row < E) ? rbf0[(size_t)row * 6 + q] : 0.f;
    }
    for (int i = tid; i < 128 * 32; i += 512) {
        int k = i >> 5, c4 = (i & 31) * 4;
        *(float4*)&Bs[k * RP + c4] = *(const float4*)&Wji[k * 128 + c4];
    }
    __syncthreads();

    u64 acc[4][4];
    gemmRx8<4, 128>(As, Bs, bji, r0, c0, acc);
#pragma unroll
    for (int i = 0; i < 4; i++) {
        int row = tile0 + r0 + i;
        float2 p0 = unpack2(acc[i][0]), p1 = unpack2(acc[i][1]);
        float2 p2 = unpack2(acc[i][2]), p3 = unpack2(acc[i][3]);
        *(float4*)&g_xji[(size_t)row * 128 + c0] =
            make_float4(silu_(p0.x), silu_(p0.y), silu_(p1.x), silu_(p1.y));
        *(float4*)&g_xji[(size_t)row * 128 + c0 + 4] =
            make_float4(silu_(p2.x), silu_(p2.y), silu_(p3.x), silu_(p3.y));
    }
    __syncthreads();
    for (int i = tid; i < 128 * 32; i += 512) {
        int k = i >> 5, c4 = (i & 31) * 4;
        *(float4*)&Bs[k * RP + c4] = *(const float4*)&Wkj[k * 128 + c4];
    }
    __syncthreads();
    gemmRx8<4, 128>(As, Bs, bkj, r0, c0, acc);
    __syncthreads();
#pragma unroll
    for (int i = 0; i < 4; i++) {
        float rv[6];
#pragma unroll
        for (int q = 0; q < 6; q++) rv[q] = Rb[(r0 + i) * 8 + q];
        float* d = &As[(r0 + i) * RP + c0];
#pragma unroll
        for (int jp = 0; jp < 4; jp++) {
            float2 p = unpack2(acc[i][jp]);
            int cA = c0 + 2 * jp;
            float f0 = 0.f, f1 = 0.f;
#pragma unroll
            for (int q = 0; q < 6; q++) {
                f0 += rv[q] * Wc[q * 128 + cA];
                f1 += rv[q] * Wc[q * 128 + cA + 1];
            }
            d[2 * jp] = silu_(p.x) * f0;
            d[2 * jp + 1] = silu_(p.y) * f1;
        }
    }
    __syncthreads();
    for (int i = tid; i < 128 * 16; i += 512) {
        int k = i >> 4, c4 = (i & 15) * 4;
        *(float4*)&Bs[k * RP + c4] = *(const float4*)&Wdown[k * 64 + c4];
    }
    __syncthreads();
    u64 a2[2][4];
    const int rr0 = (tid >> 3) * 2, cc0 = (tid & 7) * 8;
    gemmRx8<2, 128>(As, Bs, (const float*)0, rr0, cc0, a2);
#pragma unroll
    for (int i = 0; i < 2; i++) {
        int row = tile0 + rr0 + i;
        float2 p0 = unpack2(a2[i][0]), p1 = unpack2(a2[i][1]);
        float2 p2 = unpack2(a2[i][2]), p3 = unpack2(a2[i][3]);
        *(float4*)&g_xkjd[(size_t)row * 64 + cc0] =
            make_float4(silu_(p0.x), silu_(p0.y), silu_(p1.x), silu_(p1.y));
        *(float4*)&g_xkjd[(size_t)row * 64 + cc0 + 4] =
            make_float4(silu_(p2.x), silu_(p2.y), silu_(p3.x), silu_(p3.y));
    }
}

// ---------------- K2: persistent triplet messages + scatter ----------------
__global__ void __launch_bounds__(256)
k_triplet(const float* __restrict__ sbf, const float* __restrict__ tb,
          const int* __restrict__ idx_kj, const int* __restrict__ idx_ji,
          const float* __restrict__ Ws1, const float* __restrict__ Ws2,
          const float* __restrict__ Wt1, const float* __restrict__ Wt2,
          int T, int nchunks) {
    float* smf = (float*)smraw;
    float* TB  = smf;
    float* SB  = TB + 32 * 296;
    float* W1T = SB + 32 * 44;
    float* S1T = W1T + 8 * 300;
    float* WT2 = S1T + 8 * 44;
    float* WS2 = WT2 + 512;
    float* TMT = WS2 + 512;
    float* TMS = TMT + 256;
    int* IK = (int*)(TMS + 256);
    int* IJ = IK + 32;
    const int tid = threadIdx.x;

    for (int i = tid; i < 8 * 300; i += 256) { int c = i / 300, r = i - 300 * c; W1T[i] = (r < 294) ? Wt1[r * 8 + c] : 0.f; }
    for (int i = tid; i < 8 * 44; i += 256)  { int c = i / 44,  r = i - 44 * c;  S1T[i] = (r < 42)  ? Ws1[r * 8 + c] : 0.f; }
    for (int i = tid; i < 512; i += 256) { WT2[i] = Wt2[i]; WS2[i] = Ws2[i]; }
    if (tid < 32) {
        TB[tid * 296 + 294] = 0.f; TB[tid * 296 + 295] = 0.f;
        SB[tid * 44 + 42] = 0.f;   SB[tid * 44 + 43] = 0.f;
    }
    __syncthreads();

    const int tr = tid >> 3, c = tid & 7;
    const int c8 = (tid & 7) * 8;

    for (int ch = blockIdx.x; ch < nchunks; ch += gridDim.x) {
        const int t0 = ch * 32;
        int nrows = T - t0; if (nrows > 32) nrows = 32;

        if (tid < 32) {
            int t = t0 + tid;
            IK[tid] = (t < T) ? idx_kj[t] : 0;
            IJ[tid] = (t < T) ? idx_ji[t] : 0;
        }
        {
            const float* src = tb + (size_t)t0 * 294;
            int lim = nrows * 294;
            for (int i4 = tid; i4 < 2352; i4 += 256) {
                int e = i4 * 4; float vv[4] = {0.f, 0.f, 0.f, 0.f};
                if (e + 4 <= lim) { float4 v = *(const float4*)(src + e); vv[0] = v.x; vv[1] = v.y; vv[2] = v.z; vv[3] = v.w; }
                else { for (int j = 0; j < 4; j++) if (e + j < lim) vv[j] = src[e + j]; }
#pragma unroll
                for (int j = 0; j < 4; j++) { int ee = e + j; int r = ee / 294, cc = ee - 294 * r; TB[r * 296 + cc] = vv[j]; }
            }
            const float* ss = sbf + (size_t)t0 * 42;
            int lim2 = nrows * 42;
            for (int i4 = tid; i4 < 336; i4 += 256) {
                int e = i4 * 4; float vv[4] = {0.f, 0.f, 0.f, 0.f};
                if (e + 4 <= lim2) { float4 v = *(const float4*)(ss + e); vv[0] = v.x; vv[1] = v.y; vv[2] = v.z; vv[3] = v.w; }
                else { for (int j = 0; j < 4; j++) if (e + j < lim2) vv[j] = ss[e + j]; }
#pragma unroll
                for (int j = 0; j < 4; j++) { int ee = e + j; int r = ee / 42, cc = ee - 42 * r; SB[r * 44 + cc] = vv[j]; }
            }
        }
        __syncthreads();
        {
            const ulonglong2* a = (const ulonglong2*)(TB + tr * 296);
            const ulonglong2* w = (const ulonglong2*)(W1T + c * 300);
            u64 ac0 = 0, ac1 = 0;
#pragma unroll 4
            for (int r = 0; r < 74; r++) { ulonglong2 x = a[r], y = w[r]; ffma2(ac0, x.x, y.x); ffma2(ac1, x.y, y.y); }
            float2 p = unpack2(ac0), q = unpack2(ac1);
            TMT[tr * 8 + c] = p.x + p.y + q.x + q.y;
            const ulonglong2* s2 = (const ulonglong2*)(SB + tr * 44);
            const ulonglong2* w2 = (const ulonglong2*)(S1T + c * 44);
            u64 b0 = 0, b1 = 0;
#pragma unroll
            for (int r = 0; r < 11; r++) { ulonglong2 x = s2[r], y = w2[r]; ffma2(b0, x.x, y.x); ffma2(b1, x.y, y.y); }
            float2 s = unpack2(b0), t2 = unpack2(b1);
            TMS[tr * 8 + c] = s.x + s.y + t2.x + t2.y;
        }
        __syncthreads();
        if (t0 + tr < T) {
            u64 tp[4] = {0, 0, 0, 0}, sp[4] = {0, 0, 0, 0};
#pragma unroll
            for (int r = 0; r < 8; r++) {
                float at = TMT[tr * 8 + r], bs = TMS[tr * 8 + r];
                u64 a = pack2(at, at), b = pack2(bs, bs);
                const ulonglong2* w2 = (const ulonglong2*)(WT2 + r * 64 + c8);
                const ulonglong2* v2 = (const ulonglong2*)(WS2 + r * 64 + c8);
                ulonglong2 wA = w2[0], wB = w2[1], vA = v2[0], vB = v2[1];
                ffma2(tp[0], a, wA.x); ffma2(tp[1], a, wA.y); ffma2(tp[2], a, wB.x); ffma2(tp[3], a, wB.y);
                ffma2(sp[0], b, vA.x); ffma2(sp[1], b, vA.y); ffma2(sp[2], b, vB.x); ffma2(sp[3], b, vB.y);
            }
            size_t gk = (size_t)IK[tr] * 64 + c8;
            float4 g0 = *(const float4*)&g_xkjd[gk];
            float4 g1 = *(const float4*)&g_xkjd[gk + 4];
            float gg[8] = {g0.x, g0.y, g0.z, g0.w, g1.x, g1.y, g1.z, g1.w};
            float* dst = &g_agg[(size_t)IJ[tr] * 64 + c8];
#pragma unroll
            for (int jp = 0; jp < 4; jp++) {
                float2 tv = unpack2(tp[jp]), sv = unpack2(sp[jp]);
                atomicAdd(dst + 2 * jp,     tv.x * sv.x * gg[2 * jp]);
                atomicAdd(dst + 2 * jp + 1, tv.y * sv.y * gg[2 * jp + 1]);
            }
        }
        __syncthreads();
    }
}

// ---------------- K3: wmma bf16x3 edge epilogue chain (256 threads) ----------------
// SMEM byte offsets
#define OFF_VH 0
#define OFF_VL 34816
#define OFF_TH 69632
#define OFF_TL 104448
#define OFF_WH 139264
#define OFF_WL 174080
#define OFF_F  208896
#define OFF_BS 219136
#define SM_POST (219136 + 9728)

typedef wmma::fragment<wmma::accumulator, 16, 16, 16, float> AccFrag;

__device__ __forceinline__ void mma_stage(int w, int ksteps,
        const __nv_bfloat16* Ah, const __nv_bfloat16* Al,
        const __nv_bfloat16* Wh, const __nv_bfloat16* Wl,
        AccFrag (&acc)[8]) {
#pragma unroll
    for (int j = 0; j < 8; j++) wmma::fill_fragment(acc[j], 0.f);
    for (int kk = 0; kk < ksteps; kk++) {
        wmma::fragment<wmma::matrix_a, 16, 16, 16, __nv_bfloat16, wmma::row_major> ah, al;
        wmma::load_matrix_sync(ah, Ah + w * 16 * LDB + kk * 16, LDB);
        wmma::load_matrix_sync(al, Al + w * 16 * LDB + kk * 16, LDB);
#pragma unroll
        for (int j = 0; j < 8; j++) {
            wmma::fragment<wmma::matrix_b, 16, 16, 16, __nv_bfloat16, wmma::row_major> bh, bl;
            wmma::load_matrix_sync(bh, Wh + kk * 16 * LDB + j * 16, LDB);
            wmma::load_matrix_sync(bl, Wl + kk * 16 * LDB + j * 16, LDB);
            wmma::mma_sync(acc[j], ah, bh, acc[j]);
            wmma::mma_sync(acc[j], ah, bl, acc[j]);
            wmma::mma_sync(acc[j], al, bh, acc[j]);
        }
    }
}

__global__ void __launch_bounds__(256, 1)
k_post_wmma(const float* __restrict__ x1, const float* __restrict__ rbf0,
            const float* __restrict__ Wr_g,
            const float* __restrict__ rbb1, const float* __restrict__ rbb2,
            const float* __restrict__ blin,
            const float* __restrict__ rab1, const float* __restrict__ rab2,
            float* __restrict__ out, int E) {
    char* sm = smraw;
    __nv_bfloat16* Vh = (__nv_bfloat16*)(sm + OFF_VH);
    __nv_bfloat16* Vl = (__nv_bfloat16*)(sm + OFF_VL);
    __nv_bfloat16* Th = (__nv_bfloat16*)(sm + OFF_TH);
    __nv_bfloat16* Tl = (__nv_bfloat16*)(sm + OFF_TL);
    __nv_bfloat16* Wh = (__nv_bfloat16*)(sm + OFF_WH);
    __nv_bfloat16* Wl = (__nv_bfloat16*)(sm + OFF_WL);
    float* F   = (float*)(sm + OFF_F);
    float* bsm = (float*)(sm + OFF_BS);
    const uint32_t WhU = smem_to_u32(Wh), WlU = smem_to_u32(Wl);
    const int tid = threadIdx.x;
    const int w = tid >> 5;
    const int tile0 = blockIdx.x * 128;

    // biases, Wr, per-row rbf
    if (tid < 128) {
        int i = tid;
        bsm[i] = rbb1[i]; bsm[128 + i] = rbb2[i]; bsm[256 + i] = blin[i];
        bsm[384 + i] = rab1[i]; bsm[512 + i] = rab2[i];
        bsm[640 + i] = rab1[128 + i]; bsm[768 + i] = rab2[128 + i];
    }
    for (int i = tid; i < 768; i += 256) bsm[896 + i] = Wr_g[i];
    for (int i = tid; i < 768; i += 256) {
        int r = i / 6, q = i - 6 * r;
        int row = tile0 + r;
        bsm[1664 + i] = (row < E) ? rbf0[(size_t)row * 6 + q] : 0.f;
    }
    // agg -> T (fp32 -> bf16 hi/lo), rows padded in g_agg
    {
        int r = tid >> 1, cb = (tid & 1) * 32;
        const float4* ag = (const float4*)&g_agg[(size_t)(tile0 + r) * 64 + cb];
#pragma unroll
        for (int u = 0; u < 8; u++) {
            float4 v = ag[u];
            int c = cb + u * 4;
            stsPairE(Th, Tl, r * LDB + c, v.x, v.y);
            stsPairE(Th, Tl, r * LDB + c + 2, v.z, v.w);
        }
    }
    // W <- Wup
    cpW(WhU, WlU, (const char*)g_Wuph, (const char*)g_Wupl, 64 * LDB * 2, tid);
    CP_COMMIT(); CP_WAIT0();
    __syncthreads();

    AccFrag acc[8];
    const int WB = 128 * LDB * 2;  // bytes per K=128 weight image

#define EPILOGUE(MODE, BO, DH, DL, NXT_H, NXT_L, NXT_B) do {                        \
    __syncthreads();                                                                \
    if (NXT_B) cpW(WhU, WlU, (const char*)(NXT_H), (const char*)(NXT_L), NXT_B, tid); \
    CP_COMMIT();                                                                    \
    for (int j = 0; j < 8; j++) {                                                   \
        wmma::store_matrix_sync(F + w * 16 * 20, acc[j], 20, wmma::mem_row_major);  \
        __syncthreads();                                                            \
        int row = tid >> 1, cb = (tid & 1) * 8, col = j * 16 + cb;                  \
        int grow = tile0 + row;                                                     \
        float d[8];                                                                 \
        _Pragma("unroll") for (int u = 0; u < 8; u++) d[u] = F[row * 20 + cb + u];  \
        float v[8];                                                                 \
        if (MODE == 0) {                                                            \
            float4 x0 = *(const float4*)&g_xji[(size_t)grow * 128 + col];           \
            float4 x1v = *(const float4*)&g_xji[(size_t)grow * 128 + col + 4];      \
            float xj[8] = {x0.x, x0.y, x0.z, x0.w, x1v.x, x1v.y, x1v.z, x1v.w};     \
            _Pragma("unroll") for (int u = 0; u < 8; u++) v[u] = xj[u] + silu_(d[u]); \
        } else if (MODE == 1) {                                                     \
            _Pragma("unroll") for (int u = 0; u < 8; u++) v[u] = silu_(d[u] + bsm[(BO) + col + u]); \
        } else if (MODE == 2) {                                                     \
            _Pragma("unroll") for (int u = 0; u < 8; u += 2) {                      \
                float2 o = ldPairE(Vh, Vl, row * LDB + col + u);                    \
                v[u]     = o.x + silu_(d[u] + bsm[(BO) + col + u]);                 \
                v[u + 1] = o.y + silu_(d[u + 1] + bsm[(BO) + col + u + 1]);         \
            }                                                                       \
        } else {                                                                    \
            bool ok = grow < E;                                                     \
            float xr[8] = {0, 0, 0, 0, 0, 0, 0, 0};                                 \
            if (ok) {                                                               \
                float4 x0 = *(const float4*)&x1[(size_t)grow * 128 + col];          \
                float4 x1v = *(const float4*)&x1[(size_t)grow * 128 + col + 4];     \
                xr[0] = x0.x; xr[1] = x0.y; xr[2] = x0.z; xr[3] = x0.w;             \
                xr[4] = x1v.x; xr[5] = x1v.y; xr[6] = x1v.z; xr[7] = x1v.w;         \
            }                                                                       \
            _Pragma("unroll") for (int u = 0; u < 8; u++) v[u] = silu_(d[u] + bsm[(BO) + col + u]) + xr[u]; \
        }                                                                           \
        _Pragma("unroll") for (int u = 0; u < 8; u += 2)                            \
            stsPairE(DH, DL, row * LDB + col + u, v[u], v[u + 1]);                  \
        __syncthreads();                                                            \
    }                                                                               \
    CP_WAIT0();                                                                     \
    __syncthreads();                                                                \
} while (0)

    // s0: D = agg @ Wup ; V = xji + silu(D)
    mma_stage(w, 4, Th, Tl, Wh, Wl, acc);
    EPILOGUE(0, 0, Vh, Vl, g_Wph, g_Wpl, WB);
    // s1: D = V @ rbW1 ; T = silu(D + rbb1)
    mma_stage(w, 8, Vh, Vl, Wh, Wl, acc);
    EPILOGUE(1, 0, Th, Tl, g_Wph + 128 * LDB, g_Wpl + 128 * LDB, WB);
    // s2: D = T @ rbW2 ; V += silu(D + rbb2)
    mma_stage(w, 8, Th, Tl, Wh, Wl, acc);
    EPILOGUE(2, 128, Vh, Vl, g_Wph + 2 * 128 * LDB, g_Wpl + 2 * 128 * LDB, WB);
    // s3: D = V @ Wlin ; V = silu(D + blin) + x1
    mma_stage(w, 8, Vh, Vl, Wh, Wl, acc);
    EPILOGUE(3, 256, Vh, Vl, g_Wph + 3 * 128 * LDB, g_Wpl + 3 * 128 * LDB, WB);
    // s4: raW1a
    mma_stage(w, 8, Vh, Vl, Wh, Wl, acc);
    EPILOGUE(1, 384, Th, Tl, g_Wph + 4 * 128 * LDB, g_Wpl + 4 * 128 * LDB, WB);
    // s5: raW2a
    mma_stage(w, 8, Th, Tl, Wh, Wl, acc);
    EPILOGUE(2, 512, Vh, Vl, g_Wph + 5 * 128 * LDB, g_Wpl + 5 * 128 * LDB, WB);
    // s6: raW1b
    mma_stage(w, 8, Vh, Vl, Wh, Wl, acc);
    EPILOGUE(1, 640, Th, Tl, g_Wph + 6 * 128 * LDB, g_Wpl + 6 * 128 * LDB, WB);
    // s7: raW2b
    mma_stage(w, 8, Th, Tl, Wh, Wl, acc);
    EPILOGUE(2, 768, Vh, Vl, (const __nv_bfloat16*)0, (const __nv_bfloat16*)0, 0);

    // out: e1 = V, e2 = (rbf0 @ W_rbf) * V
    for (int i = tid; i < 128 * 32; i += 256) {
        int rr = i >> 5, cb = (i & 31) * 4;
        int grow = tile0 + rr;
        if (grow >= E) continue;
        float2 p0 = ldPairE(Vh, Vl, rr * LDB + cb);
        float2 p1 = ldPairE(Vh, Vl, rr * LDB + cb + 2);
        float rv[6];
#pragma unroll
        for (int q = 0; q < 6; q++) rv[q] = bsm[1664 + rr * 6 + q];
        float e1v[4] = {p0.x, p0.y, p1.x, p1.y};
        float e2v[4];
#pragma unroll
        for (int u = 0; u < 4; u++) {
            float f = 0.f;
#pragma unroll
            for (int q = 0; q < 6; q++) f += rv[q] * bsm[896 + q * 128 + cb + u];
            e2v[u] = f * e1v[u];
        }
        *(float4*)&out[(size_t)grow * 128 + cb] = make_float4(e1v[0], e1v[1], e1v[2], e1v[3]);
        *(float4*)&out[((size_t)E + grow) * 128 + cb] = make_float4(e2v[0], e2v[1], e2v[2], e2v[3]);
    }
}

extern "C" void kernel_launch(void* const* d_in, const int* in_sizes, int n_in,
                              void* d_out, int out_size) {
    const float* x1    = (const float*)d_in[0];
    const float* rbf0  = (const float*)d_in[1];
    const float* sbf   = (const float*)d_in[2];
    const float* tb    = (const float*)d_in[3];
    const int* idx_kj  = (const int*)d_in[4];
    const int* idx_ji  = (const int*)d_in[5];
    const float* W_rbf1 = (const float*)d_in[6];
    const float* W_rbf2 = (const float*)d_in[7];
    const float* W_sbf1 = (const float*)d_in[8];
    const float* W_sbf2 = (const float*)d_in[9];
    const float* W_t1   = (const float*)d_in[10];
    const float* W_t2   = (const float*)d_in[11];
    const float* W_rbf  = (const float*)d_in[12];
    const float* W_kj   = (const float*)d_in[13];
    const float* b_kj   = (const float*)d_in[14];
    const float* W_ji   = (const float*)d_in[15];
    const float* b_ji   = (const float*)d_in[16];
    const float* W_down = (const float*)d_in[17];
    const float* W_up   = (const float*)d_in[18];
    const float* rbW1   = (const float*)d_in[19];
    const float* rbb1   = (const float*)d_in[20];
    const float* rbW2   = (const float*)d_in[21];
    const float* rbb2   = (const float*)d_in[22];
    const float* W_lin  = (const float*)d_in[23];
    const float* b_lin  = (const float*)d_in[24];
    const float* raW1   = (const float*)d_in[25];
    const float* rab1   = (const float*)d_in[26];
    const float* raW2   = (const float*)d_in[27];
    const float* rab2   = (const float*)d_in[28];
    float* out = (float*)d_out;

    const int E = in_sizes[0] / 128;
    const int T = in_sizes[4];
    const int SM_PRE = (2 * 128 * RP + 768 + 1024) * 4;
    const int SM_TRI = 60928;
    const int etiles = (E + 127) / 128;
    const int nchunks = (T + 31) / 32;
    const int nprep = 7 * 128 * LDB + 64 * LDB;

    cudaFuncSetAttribute(k_edge_pre,  cudaFuncAttributeMaxDynamicSharedMemorySize, SM_PRE);
    cudaFuncSetAttribute(k_triplet,   cudaFuncAttributeMaxDynamicSharedMemorySize, SM_TRI);
    cudaFuncSetAttribute(k_post_wmma, cudaFuncAttributeMaxDynamicSharedMemorySize, SM_POST);

    k_wcomb<<<3, 256>>>(W_rbf1, W_rbf2);
    k_wprep<<<(nprep + 255) / 256, 256>>>(rbW1, rbW2, W_lin, raW1, raW2, W_up);
    k_edge_pre<<<etiles, 512, SM_PRE>>>(x1, rbf0, W_ji, b_ji, W_kj, b_kj, W_down, E);
    k_triplet<<<444, 256, SM_TRI>>>(sbf, tb, idx_kj, idx_ji, W_sbf1, W_sbf2, W_t1, W_t2, T, nchunks);
    k_post_wmma<<<etiles, 256, SM_POST>>>(x1, rbf0, W_rbf, rbb1, rbb2, b_lin, rab1, rab2, out, E);
}